// round 1
// baseline (speedup 1.0000x reference)
#include <cuda_runtime.h>

#define NN 50000
#define NE 800000
#define DD 128
#define BM 64

// Scratch (allocation-free rule: __device__ globals)
__device__ float g_h[NN * DD];      // projected node features
__device__ float g_degs[NN];        // in-degree + 1
__device__ float g_norm[NN];        // degs^-0.5
__device__ float g_Wt[DD * DD];     // W transposed: Wt[k][d] = W[d][k]

__global__ void k_init_degs() {
    int i = blockIdx.x * blockDim.x + threadIdx.x;
    if (i < NN) g_degs[i] = 1.0f;
}

__global__ void k_count(const int* __restrict__ dst) {
    int e = blockIdx.x * blockDim.x + threadIdx.x;
    if (e < NE) atomicAdd(&g_degs[dst[e]], 1.0f);
}

__global__ void k_norm() {
    int i = blockIdx.x * blockDim.x + threadIdx.x;
    if (i < NN) g_norm[i] = rsqrtf(g_degs[i]);
}

__global__ void k_transpose(const float* __restrict__ W) {
    int i = blockIdx.x * blockDim.x + threadIdx.x;   // 0..16383
    if (i < DD * DD) {
        int d = i >> 7, k = i & 127;
        g_Wt[k * DD + d] = W[i];                     // coalesced read, strided write (64KB, trivial)
    }
}

// h = nfeat @ W^T + b ; also writes residual branch into out.
// Block: 256 threads = 16(tx: d) x 16(ty: node). Tile: 64 nodes x 128 outputs.
// Per thread: 4 nodes x 8 outputs = 32 accumulators.
__global__ void k_gemm(const float* __restrict__ nfeat, const float* __restrict__ bias,
                       const float* __restrict__ res_w, float* __restrict__ out) {
    __shared__ float sA[BM][DD];     // 32 KB: full K resident for 64 nodes
    __shared__ float sW[32][DD];     // 16 KB: 32-row chunk of Wt

    int tid = threadIdx.x;
    int tx = tid & 15;               // d-group
    int ty = tid >> 4;               // node-group
    int m0 = blockIdx.x * BM;

    // Load node-feature tile (zero-pad past NN)
    {
        const float4* nf4 = (const float4*)nfeat;
        float4* sA4 = (float4*)&sA[0][0];
        for (int t = tid; t < BM * DD / 4; t += 256) {
            int row = t >> 5;                    // 32 float4 per row
            int n = m0 + row;
            float4 v = make_float4(0.f, 0.f, 0.f, 0.f);
            if (n < NN) v = nf4[n * 32 + (t & 31)];
            sA4[t] = v;
        }
    }

    float acc[4][8];
    #pragma unroll
    for (int i = 0; i < 4; i++)
        #pragma unroll
        for (int j = 0; j < 8; j++) acc[i][j] = 0.f;

    for (int k0 = 0; k0 < DD; k0 += 32) {
        __syncthreads();
        {   // load Wt rows k0..k0+31
            const float4* w4 = (const float4*)(g_Wt + k0 * DD);
            float4* sW4 = (float4*)&sW[0][0];
            for (int t = tid; t < 32 * DD / 4; t += 256) sW4[t] = w4[t];
        }
        __syncthreads();

        #pragma unroll
        for (int kk = 0; kk < 32; kk++) {
            float a[4], w[8];
            #pragma unroll
            for (int i = 0; i < 4; i++) a[i] = sA[ty * 4 + i][k0 + kk];
            #pragma unroll
            for (int j = 0; j < 8; j++) w[j] = sW[kk][tx + 16 * j];
            #pragma unroll
            for (int i = 0; i < 4; i++)
                #pragma unroll
                for (int j = 0; j < 8; j++)
                    acc[i][j] = fmaf(a[i], w[j], acc[i][j]);
        }
    }

    // Epilogue: h -> g_h, residual -> out
    #pragma unroll
    for (int i = 0; i < 4; i++) {
        int n = m0 + ty * 4 + i;
        if (n >= NN) continue;
        float inv = 1.0f / g_degs[n];
        #pragma unroll
        for (int j = 0; j < 8; j++) {
            int d = tx + 16 * j;
            float h = acc[i][j] + bias[d];
            g_h[n * DD + d] = h;
            out[n * DD + d] = fmaxf(h + res_w[d], 0.f) * inv;
        }
    }
}

// One warp per edge: gather h[src], add edge embedding, relu, scale by norm,
// vector-RED into out[dst]. Each lane owns 4 consecutive floats (float4).
__global__ void k_edge(const int* __restrict__ efeat, const int* __restrict__ src,
                       const int* __restrict__ dst, const float* __restrict__ eemb,
                       float* __restrict__ out) {
    int w = (blockIdx.x * blockDim.x + threadIdx.x) >> 5;
    if (w >= NE) return;
    int lane = threadIdx.x & 31;

    int s = src[w];            // broadcast loads (all lanes same addr)
    int d = dst[w];
    int t = efeat[w];
    float en = g_norm[s] * g_norm[d];

    float4 hv = ((const float4*)(g_h + s * DD))[lane];
    float4 ev = ((const float4*)(eemb + t * DD))[lane];   // 8KB table, L1/L2 hot
    float4 m;
    m.x = en * fmaxf(hv.x + ev.x, 0.f);
    m.y = en * fmaxf(hv.y + ev.y, 0.f);
    m.z = en * fmaxf(hv.z + ev.z, 0.f);
    m.w = en * fmaxf(hv.w + ev.w, 0.f);

    float* p = out + d * DD + lane * 4;
    asm volatile("red.global.add.v4.f32 [%0], {%1,%2,%3,%4};"
                 :: "l"(p), "f"(m.x), "f"(m.y), "f"(m.z), "f"(m.w) : "memory");
}

extern "C" void kernel_launch(void* const* d_in, const int* in_sizes, int n_in,
                              void* d_out, int out_size) {
    const float* nfeat = (const float*)d_in[0];
    const int*   efeat = (const int*)d_in[1];
    const int*   src   = (const int*)d_in[2];
    const int*   dst   = (const int*)d_in[3];
    const float* W     = (const float*)d_in[4];
    const float* bias  = (const float*)d_in[5];
    const float* eemb  = (const float*)d_in[6];
    const float* res_w = (const float*)d_in[7];
    float* out = (float*)d_out;

    k_init_degs<<<(NN + 255) / 256, 256>>>();
    k_count<<<(NE + 255) / 256, 256>>>(dst);
    k_norm<<<(NN + 255) / 256, 256>>>();
    k_transpose<<<(DD * DD + 255) / 256, 256>>>(W);
    k_gemm<<<(NN + BM - 1) / BM, 256>>>(nfeat, bias, res_w, out);
    k_edge<<<(NE * 32 + 255) / 256, 256>>>(efeat, src, dst, eemb, out);
}